// round 13
// baseline (speedup 1.0000x reference)
#include <cuda_runtime.h>
#include <cuda_fp16.h>
#include <math.h>
#include <stdint.h>

#define NN 50000
#define EE 800000
#define CIN 256
#define COUT 256
#define NB 49            // scan blocks of 1024: 49*1024 = 50176 >= NN

// ---------------- scratch (static device globals; no allocation) -------------
__device__ __half g_xvh[(size_t)NN * 256]; // x @ Wv + bv  (fp16 storage)
__device__ float g_hlr[NN * 8];            // [sl(4) | sr(4)] raw
__device__ float g_agg[NN * 8];            // (hlr + conv)/(1+deg)
__device__ int   g_esrc[EE];               // src indices sorted by dst (CSR)
__device__ int   g_off[NN + 1];            // CSR offsets
__device__ int   g_cur[NN];                // scatter cursors
__device__ int   g_deg[NN];                // in-degree per dst
__device__ float g_watt[8 * 256];          // rows 0..3: Wl@att_l per head; 4..7: Wr@att_r
__device__ float g_batt[8];                // bias dotted with att vectors
__device__ float g_WvT[256 * 256];         // Wv transposed: g_WvT[n][k] = Wv[k][n]
__device__ int   g_bsum[64];               // per-block degree sums
__device__ int   g_boff[64];               // exclusive scan of block sums

// ---------------- fused setup: prep (blocks 0..7), trans (8..71), zero (72..)
__global__ void k_setup(const float* __restrict__ Wl, const float* __restrict__ bl,
                        const float* __restrict__ Wr, const float* __restrict__ br,
                        const float* __restrict__ attl, const float* __restrict__ attr,
                        const float* __restrict__ Wv) {
    int b = blockIdx.x;
    if (b < 8) {
        int o = b, h = o & 3;
        const float* W   = (o < 4) ? Wl : Wr;
        const float* att = (o < 4) ? attl : attr;
        const float* bb  = (o < 4) ? bl : br;
        int c = threadIdx.x;
        float s = 0.f;
#pragma unroll 8
        for (int d = 0; d < 64; d++) s += W[c * 256 + h * 64 + d] * att[h * 64 + d];
        g_watt[o * 256 + c] = s;
        if (c == 0) {
            float sb = 0.f;
            for (int d = 0; d < 64; d++) sb += bb[h * 64 + d] * att[h * 64 + d];
            g_batt[o] = sb;
        }
    } else if (b < 72) {
        __shared__ float tile[32][33];
        int bb2 = b - 8;
        int bx = bb2 & 7, by = bb2 >> 3;
        int tx = threadIdx.x & 31, ty = threadIdx.x >> 5;
#pragma unroll
        for (int i = 0; i < 32; i += 8)
            tile[ty + i][tx] = Wv[(by * 32 + ty + i) * 256 + bx * 32 + tx];
        __syncthreads();
#pragma unroll
        for (int i = 0; i < 32; i += 8)
            g_WvT[(bx * 32 + ty + i) * 256 + by * 32 + tx] = tile[tx][ty + i];
    } else {
        int i = (b - 72) * 256 + threadIdx.x;
        if (i < NN) g_deg[i] = 0;
    }
}

// per-node raw scores: 4 threads per node, 64 k each, shfl-reduce within quad.
// 200k threads, ~40 regs, 8KB smem -> high occupancy.
__global__ void __launch_bounds__(256) k_hlr(const float* __restrict__ x) {
    __shared__ float ws[2048];
    int t = threadIdx.x;
    for (int i = t; i < 2048; i += 256) ws[i] = g_watt[i];
    __syncthreads();
    int g = blockIdx.x * 256 + t;
    int node = g >> 2, sub = g & 3;
    if (node >= NN) return;      // warp-aligned exit (200000 % 32 == 0)
    const float* xr = x + (size_t)node * 256 + sub * 64;
    const float* wr = ws + sub * 64;
    float acc[8] = {0.f, 0.f, 0.f, 0.f, 0.f, 0.f, 0.f, 0.f};
#pragma unroll
    for (int q = 0; q < 16; q += 4) {
        float4 xv[4];
#pragma unroll
        for (int u = 0; u < 4; u++) xv[u] = *(const float4*)(xr + (q + u) * 4);
#pragma unroll
        for (int o = 0; o < 8; o++) {
#pragma unroll
            for (int u = 0; u < 4; u++) {
                float4 w = *(const float4*)(wr + o * 256 + (q + u) * 4);
                acc[o] += xv[u].x * w.x + xv[u].y * w.y + xv[u].z * w.z + xv[u].w * w.w;
            }
        }
    }
#pragma unroll
    for (int o = 0; o < 8; o++) {
        acc[o] += __shfl_xor_sync(0xffffffffu, acc[o], 1);
        acc[o] += __shfl_xor_sync(0xffffffffu, acc[o], 2);
    }
    if (sub == 0) {
        float4 h0 = make_float4(acc[0] + g_batt[0], acc[1] + g_batt[1],
                                acc[2] + g_batt[2], acc[3] + g_batt[3]);
        float4 h1 = make_float4(acc[4] + g_batt[4], acc[5] + g_batt[5],
                                acc[6] + g_batt[6], acc[7] + g_batt[7]);
        *(float4*)&g_hlr[node * 8] = h0;
        *(float4*)&g_hlr[node * 8 + 4] = h1;
    }
}

__global__ void k_count(const int* __restrict__ dst) {
    int e = blockIdx.x * blockDim.x + threadIdx.x;
    if (e < EE) atomicAdd(&g_deg[dst[e]], 1);
}

// ---- parallel 3-phase exclusive scan of g_deg -> g_off, g_cur ----
__global__ void k_bsum() {                 // grid NB, block 1024
    __shared__ int ssum[32];
    int b = blockIdx.x, t = threadIdx.x;
    int i = b * 1024 + t;
    int v = (i < NN) ? g_deg[i] : 0;
#pragma unroll
    for (int o = 16; o; o >>= 1) v += __shfl_xor_sync(0xffffffffu, v, o);
    if ((t & 31) == 0) ssum[t >> 5] = v;
    __syncthreads();
    if (t < 32) {
        int s = ssum[t];
#pragma unroll
        for (int o = 16; o; o >>= 1) s += __shfl_xor_sync(0xffffffffu, s, o);
        if (t == 0) g_bsum[b] = s;
    }
}

__global__ void k_bscan() {                // 1 block, 64 threads
    __shared__ int sh[64];
    int t = threadIdx.x;
    int v = (t < NB) ? g_bsum[t] : 0;
    sh[t] = v;
    __syncthreads();
    for (int o = 1; o < 64; o <<= 1) {
        int y = (t >= o) ? sh[t - o] : 0;
        __syncthreads();
        sh[t] += y;
        __syncthreads();
    }
    if (t < NB) g_boff[t] = sh[t] - v;     // exclusive
    if (t == NB - 1) g_off[NN] = sh[NB - 1];
}

__global__ void k_scan2() {                // grid NB, block 1024
    __shared__ int wsum[32];
    int b = blockIdx.x, t = threadIdx.x, lane = t & 31, wid = t >> 5;
    int i = b * 1024 + t;
    int v = (i < NN) ? g_deg[i] : 0;
    int xsc = v;
#pragma unroll
    for (int o = 1; o < 32; o <<= 1) { int y = __shfl_up_sync(0xffffffffu, xsc, o); if (lane >= o) xsc += y; }
    if (lane == 31) wsum[wid] = xsc;
    __syncthreads();
    if (wid == 0) {
        int s = wsum[lane];
#pragma unroll
        for (int o = 1; o < 32; o <<= 1) { int y = __shfl_up_sync(0xffffffffu, s, o); if (lane >= o) s += y; }
        wsum[lane] = s;
    }
    __syncthreads();
    int prefix = g_boff[b] + (wid ? wsum[wid - 1] : 0) + xsc - v;   // exclusive
    if (i < NN) { g_off[i] = prefix; g_cur[i] = prefix; }
}

__global__ void k_scatter(const int* __restrict__ src, const int* __restrict__ dst) {
    int e = blockIdx.x * blockDim.x + threadIdx.x;
    if (e < EE) {
        int d = dst[e];
        int pos = atomicAdd(&g_cur[d], 1);
        g_esrc[pos] = src[e];
    }
}

// agg[n][f] = (hlr[n][f] + sum_in hlr[src][f]) / (1 + deg)  — 8 threads/node
__global__ void k_agg() {
    int idx = blockIdx.x * blockDim.x + threadIdx.x;
    if (idx >= NN * 8) return;
    int n = idx >> 3, f = idx & 7;
    int s = g_off[n], e = g_off[n + 1];
    float c = 0.f;
    for (int j = s; j < e; j++) c += g_hlr[g_esrc[j] * 8 + f];
    g_agg[idx] = (g_hlr[idx] + c) / (1.0f + (float)(e - s));
}

// ---------------- tf32 mma.sync GEMM: g_xvh = half(x @ Wv + bv) --------------
__device__ __forceinline__ uint32_t f2tf(float f) {
    uint32_t u;
    asm("cvt.rna.tf32.f32 %0, %1;" : "=r"(u) : "f"(f));
    return u;
}

__global__ void __launch_bounds__(256) k_gemm_mma(const float* __restrict__ A,
                                                  const float* __restrict__ bias) {
    __shared__ uint32_t As[4096];   // [kstep(4)][mtile(8)][reg(4)][lane(32)]
    __shared__ uint32_t Bs[4096];   // [kstep(4)][ntile(16)][reg(2)][lane(32)]
    int t = threadIdx.x, lane = t & 31, wid = t >> 5;
    int row0 = (int)(blockIdx.x >> 1) * 128;
    int col0 = (int)(blockIdx.x & 1) * 128;
    int warp_m = wid & 1, warp_n = wid >> 1;

    float acc[4][4][4];
#pragma unroll
    for (int mt = 0; mt < 4; mt++)
#pragma unroll
        for (int nt = 0; nt < 4; nt++)
#pragma unroll
            for (int j = 0; j < 4; j++) acc[mt][nt][j] = 0.f;

    int sAaddr[4], sBaddr[4], aRow[4], bRow[4], abCol[4];
#pragma unroll
    for (int l = 0; l < 4; l++) {
        int i = t + l * 256;
        int r = i >> 3, cq = i & 7;
        aRow[l] = r; bRow[l] = r; abCol[l] = cq * 4;
        int ks = cq >> 1, u = cq & 1;
        int mtile = r >> 4, h = (r >> 3) & 1, g = r & 7;
        sAaddr[l] = ((ks * 8 + mtile) * 4 + (h + 2 * u)) * 32 + g * 4;
        int ntile = r >> 3;
        sBaddr[l] = ((ks * 16 + ntile) * 2 + u) * 32 + (r & 7) * 4;
    }

    uint4 ap[4], bp[4];
#pragma unroll
    for (int l = 0; l < 4; l++) {
        int grow = row0 + aRow[l];
        float4 v = make_float4(0.f, 0.f, 0.f, 0.f);
        if (grow < NN) v = *(const float4*)(A + (size_t)grow * 256 + abCol[l]);
        ap[l] = make_uint4(f2tf(v.x), f2tf(v.y), f2tf(v.z), f2tf(v.w));
        float4 w = *(const float4*)(g_WvT + (size_t)(col0 + bRow[l]) * 256 + abCol[l]);
        bp[l] = make_uint4(f2tf(w.x), f2tf(w.y), f2tf(w.z), f2tf(w.w));
    }

    for (int c = 0; c < 8; c++) {
#pragma unroll
        for (int l = 0; l < 4; l++) {
            *(uint4*)&As[sAaddr[l]] = ap[l];
            *(uint4*)&Bs[sBaddr[l]] = bp[l];
        }
        __syncthreads();
        if (c < 7) {
            int k0 = (c + 1) * 32;
#pragma unroll
            for (int l = 0; l < 4; l++) {
                int grow = row0 + aRow[l];
                float4 v = make_float4(0.f, 0.f, 0.f, 0.f);
                if (grow < NN) v = *(const float4*)(A + (size_t)grow * 256 + k0 + abCol[l]);
                ap[l] = make_uint4(f2tf(v.x), f2tf(v.y), f2tf(v.z), f2tf(v.w));
                float4 w = *(const float4*)(g_WvT + (size_t)(col0 + bRow[l]) * 256 + k0 + abCol[l]);
                bp[l] = make_uint4(f2tf(w.x), f2tf(w.y), f2tf(w.z), f2tf(w.w));
            }
        }
#pragma unroll
        for (int ks = 0; ks < 4; ks++) {
            uint32_t a[4][4], b[4][2];
#pragma unroll
            for (int mt = 0; mt < 4; mt++)
#pragma unroll
                for (int rg = 0; rg < 4; rg++)
                    a[mt][rg] = As[((ks * 8 + warp_m * 4 + mt) * 4 + rg) * 32 + lane];
#pragma unroll
            for (int nt = 0; nt < 4; nt++)
#pragma unroll
                for (int rg = 0; rg < 2; rg++)
                    b[nt][rg] = Bs[((ks * 16 + warp_n * 4 + nt) * 2 + rg) * 32 + lane];
#pragma unroll
            for (int mt = 0; mt < 4; mt++)
#pragma unroll
                for (int nt = 0; nt < 4; nt++) {
                    asm volatile(
                        "mma.sync.aligned.m16n8k8.row.col.f32.tf32.tf32.f32 "
                        "{%0,%1,%2,%3}, {%4,%5,%6,%7}, {%8,%9}, {%0,%1,%2,%3};"
                        : "+f"(acc[mt][nt][0]), "+f"(acc[mt][nt][1]),
                          "+f"(acc[mt][nt][2]), "+f"(acc[mt][nt][3])
                        : "r"(a[mt][0]), "r"(a[mt][1]), "r"(a[mt][2]), "r"(a[mt][3]),
                          "r"(b[nt][0]), "r"(b[nt][1]));
                }
        }
        __syncthreads();
    }

    int g = lane >> 2, tig = lane & 3;
#pragma unroll
    for (int mt = 0; mt < 4; mt++) {
        int rbase = row0 + warp_m * 64 + mt * 16;
#pragma unroll
        for (int h = 0; h < 2; h++) {
            int grow = rbase + h * 8 + g;
            if (grow < NN) {
                __half* orow = g_xvh + (size_t)grow * 256;
#pragma unroll
                for (int nt = 0; nt < 4; nt++) {
                    int col = col0 + warp_n * 32 + nt * 8 + tig * 2;
                    float2 o;
                    o.x = acc[mt][nt][h * 2 + 0] + bias[col];
                    o.y = acc[mt][nt][h * 2 + 1] + bias[col + 1];
                    *(__half2*)(orow + col) = __floats2half2_rn(o.x, o.y);
                }
            }
        }
    }
}

// ---------------- attention + output (warp per dst node, no max pass) -------
__global__ void k_out(float* __restrict__ out) {
    int gw = (blockIdx.x * blockDim.x + threadIdx.x) >> 5;
    int lane = threadIdx.x & 31;
    if (gw >= NN) return;
    int s0 = g_off[gw], s1 = g_off[gw + 1];
    float4* orow = (float4*)(out + (size_t)gw * 256);
    if (s0 == s1) {
        float4 z = make_float4(0.f, 0.f, 0.f, 0.f);
        orow[lane] = z; orow[lane + 32] = z;
        return;
    }
    float srh[4];
#pragma unroll
    for (int h = 0; h < 4; h++) srh[h] = g_agg[gw * 8 + 4 + h];

    // single fused pass: exp(e) (no max shift; |e| bounded), denom, weighted xv
    float den0 = 0.f, den1 = 0.f, den2 = 0.f, den3 = 0.f;
    float4 acc0 = make_float4(0.f, 0.f, 0.f, 0.f);
    float4 acc1 = acc0;
    bool hi = (lane & 16) != 0;
    for (int j = s0; j < s1; j++) {
        int s = g_esrc[j];
        float e0 = g_agg[s * 8 + 0] + srh[0]; e0 = e0 > 0.f ? e0 : 0.2f * e0;
        float e1 = g_agg[s * 8 + 1] + srh[1]; e1 = e1 > 0.f ? e1 : 0.2f * e1;
        float e2 = g_agg[s * 8 + 2] + srh[2]; e2 = e2 > 0.f ? e2 : 0.2f * e2;
        float e3 = g_agg[s * 8 + 3] + srh[3]; e3 = e3 > 0.f ? e3 : 0.2f * e3;
        float x0 = __expf(e0);
        float x1 = __expf(e1);
        float x2 = __expf(e2);
        float x3 = __expf(e3);
        den0 += x0; den1 += x1; den2 += x2; den3 += x3;
        const uint2* vr = (const uint2*)(g_xvh + (size_t)s * 256);
        uint2 p0 = vr[lane], p1 = vr[lane + 32];
        float2 a0 = __half22float2(*(__half2*)&p0.x);
        float2 a1 = __half22float2(*(__half2*)&p0.y);
        float2 b0 = __half22float2(*(__half2*)&p1.x);
        float2 b1 = __half22float2(*(__half2*)&p1.y);
        float w0 = hi ? x1 : x0;
        float w1 = hi ? x3 : x2;
        acc0.x += w0 * a0.x; acc0.y += w0 * a0.y; acc0.z += w0 * a1.x; acc0.w += w0 * a1.y;
        acc1.x += w1 * b0.x; acc1.y += w1 * b0.y; acc1.z += w1 * b1.x; acc1.w += w1 * b1.y;
    }
    float d0 = hi ? den1 : den0;
    float d1 = hi ? den3 : den2;
    float i0 = 1.f / fmaxf(d0, 1e-16f);
    float i1 = 1.f / fmaxf(d1, 1e-16f);
    acc0.x *= i0; acc0.y *= i0; acc0.z *= i0; acc0.w *= i0;
    acc1.x *= i1; acc1.y *= i1; acc1.z *= i1; acc1.w *= i1;
    orow[lane] = acc0;
    orow[lane + 32] = acc1;
}

// ---------------- launch ----------------
extern "C" void kernel_launch(void* const* d_in, const int* in_sizes, int n_in,
                              void* d_out, int out_size) {
    const float* x    = (const float*)d_in[0];
    const int*   src  = (const int*)d_in[1];
    const int*   dst  = (const int*)d_in[2];
    const float* Wl   = (const float*)d_in[3];
    const float* bl   = (const float*)d_in[4];
    const float* Wr   = (const float*)d_in[5];
    const float* br   = (const float*)d_in[6];
    const float* Wv   = (const float*)d_in[7];
    const float* bv   = (const float*)d_in[8];
    const float* attl = (const float*)d_in[9];
    const float* attr = (const float*)d_in[10];
    float* out = (float*)d_out;

    k_setup<<<72 + (NN + 255) / 256, 256>>>(Wl, bl, Wr, br, attl, attr, Wv);
    k_hlr<<<(NN * 4 + 255) / 256, 256>>>(x);
    k_count<<<(EE + 255) / 256, 256>>>(dst);
    k_bsum<<<NB, 1024>>>();
    k_bscan<<<1, 64>>>();
    k_scan2<<<NB, 1024>>>();
    k_scatter<<<(EE + 255) / 256, 256>>>(src, dst);
    k_gemm_mma<<<((NN + 127) / 128) * 2, 256>>>(x, bv);
    k_agg<<<(NN * 8 + 255) / 256, 256>>>();
    k_out<<<(NN * 32 + 255) / 256, 256>>>(out);
}

// round 14
// speedup vs baseline: 1.0935x; 1.0935x over previous
#include <cuda_runtime.h>
#include <cuda_fp16.h>
#include <math.h>
#include <stdint.h>

#define NN 50000
#define EE 800000
#define CIN 256
#define COUT 256
#define NB 49            // scan blocks of 1024: 49*1024 = 50176 >= NN

// ---------------- scratch (static device globals; no allocation) -------------
__device__ __half g_xvh[(size_t)NN * 256]; // x @ Wv + bv  (fp16 storage)
__device__ float g_hlr[NN * 8];            // [sl(4) | sr(4)] raw
__device__ float g_agg[NN * 8];            // (hlr + conv)/(1+deg)
__device__ int   g_esrc[EE];               // src indices sorted by dst (CSR)
__device__ int   g_off[NN + 1];            // CSR offsets
__device__ int   g_cur[NN];                // scatter cursors
__device__ int   g_deg[NN];                // in-degree per dst
__device__ float g_watt[8 * 256];          // rows 0..3: Wl@att_l per head; 4..7: Wr@att_r
__device__ float g_batt[8];                // bias dotted with att vectors
__device__ float g_WvT[256 * 256];         // Wv transposed: g_WvT[n][k] = Wv[k][n]
__device__ int   g_bsum[64];               // per-block degree sums
__device__ int   g_boff[64];               // exclusive scan of block sums

// ---------------- fused setup: prep (blocks 0..7), trans (8..71), zero (72..)
__global__ void k_setup(const float* __restrict__ Wl, const float* __restrict__ bl,
                        const float* __restrict__ Wr, const float* __restrict__ br,
                        const float* __restrict__ attl, const float* __restrict__ attr,
                        const float* __restrict__ Wv) {
    int b = blockIdx.x;
    if (b < 8) {
        int o = b, h = o & 3;
        const float* W   = (o < 4) ? Wl : Wr;
        const float* att = (o < 4) ? attl : attr;
        const float* bb  = (o < 4) ? bl : br;
        int c = threadIdx.x;
        float s = 0.f;
#pragma unroll 8
        for (int d = 0; d < 64; d++) s += W[c * 256 + h * 64 + d] * att[h * 64 + d];
        g_watt[o * 256 + c] = s;
        if (c == 0) {
            float sb = 0.f;
            for (int d = 0; d < 64; d++) sb += bb[h * 64 + d] * att[h * 64 + d];
            g_batt[o] = sb;
        }
    } else if (b < 72) {
        __shared__ float tile[32][33];
        int bb2 = b - 8;
        int bx = bb2 & 7, by = bb2 >> 3;
        int tx = threadIdx.x & 31, ty = threadIdx.x >> 5;
#pragma unroll
        for (int i = 0; i < 32; i += 8)
            tile[ty + i][tx] = Wv[(by * 32 + ty + i) * 256 + bx * 32 + tx];
        __syncthreads();
#pragma unroll
        for (int i = 0; i < 32; i += 8)
            g_WvT[(bx * 32 + ty + i) * 256 + by * 32 + tx] = tile[tx][ty + i];
    } else {
        int i = (b - 72) * 256 + threadIdx.x;
        if (i < NN) g_deg[i] = 0;
    }
}

// per-node raw scores: 4 threads per node, 64 k each, shfl-reduce within quad.
// ws packed with pitch 68 per (o,sub) 64-float segment -> sub stride 68 % 32 = 4
// banks => conflict-free LDS.128 (bank groups {0-3},{4-7},{8-11},{12-15}).
__global__ void __launch_bounds__(256) k_hlr(const float* __restrict__ x) {
    __shared__ __align__(16) float ws[32 * 68];
    int t = threadIdx.x;
    for (int i = t; i < 2048; i += 256) {
        int o = i >> 8, rem = i & 255, sub = rem >> 6, j = rem & 63;
        ws[(o * 4 + sub) * 68 + j] = g_watt[i];
    }
    __syncthreads();
    int g = blockIdx.x * 256 + t;
    int node = g >> 2, sub = g & 3;
    if (node >= NN) return;      // warp-aligned exit (200000 % 32 == 0)
    const float* xr = x + (size_t)node * 256 + sub * 64;
    const float* wr = ws + sub * 68;
    float acc[8] = {0.f, 0.f, 0.f, 0.f, 0.f, 0.f, 0.f, 0.f};
#pragma unroll
    for (int q = 0; q < 16; q += 4) {
        float4 xv[4];
#pragma unroll
        for (int u = 0; u < 4; u++) xv[u] = *(const float4*)(xr + (q + u) * 4);
#pragma unroll
        for (int o = 0; o < 8; o++) {
#pragma unroll
            for (int u = 0; u < 4; u++) {
                float4 w = *(const float4*)(wr + o * 272 + (q + u) * 4);
                acc[o] += xv[u].x * w.x + xv[u].y * w.y + xv[u].z * w.z + xv[u].w * w.w;
            }
        }
    }
#pragma unroll
    for (int o = 0; o < 8; o++) {
        acc[o] += __shfl_xor_sync(0xffffffffu, acc[o], 1);
        acc[o] += __shfl_xor_sync(0xffffffffu, acc[o], 2);
    }
    if (sub == 0) {
        float4 h0 = make_float4(acc[0] + g_batt[0], acc[1] + g_batt[1],
                                acc[2] + g_batt[2], acc[3] + g_batt[3]);
        float4 h1 = make_float4(acc[4] + g_batt[4], acc[5] + g_batt[5],
                                acc[6] + g_batt[6], acc[7] + g_batt[7]);
        *(float4*)&g_hlr[node * 8] = h0;
        *(float4*)&g_hlr[node * 8 + 4] = h1;
    }
}

__global__ void k_count(const int* __restrict__ dst) {
    int e = blockIdx.x * blockDim.x + threadIdx.x;
    if (e < EE) atomicAdd(&g_deg[dst[e]], 1);
}

// ---- parallel 3-phase exclusive scan of g_deg -> g_off, g_cur ----
__global__ void k_bsum() {                 // grid NB, block 1024
    __shared__ int ssum[32];
    int b = blockIdx.x, t = threadIdx.x;
    int i = b * 1024 + t;
    int v = (i < NN) ? g_deg[i] : 0;
#pragma unroll
    for (int o = 16; o; o >>= 1) v += __shfl_xor_sync(0xffffffffu, v, o);
    if ((t & 31) == 0) ssum[t >> 5] = v;
    __syncthreads();
    if (t < 32) {
        int s = ssum[t];
#pragma unroll
        for (int o = 16; o; o >>= 1) s += __shfl_xor_sync(0xffffffffu, s, o);
        if (t == 0) g_bsum[b] = s;
    }
}

__global__ void k_bscan() {                // 1 block, 64 threads
    __shared__ int sh[64];
    int t = threadIdx.x;
    int v = (t < NB) ? g_bsum[t] : 0;
    sh[t] = v;
    __syncthreads();
    for (int o = 1; o < 64; o <<= 1) {
        int y = (t >= o) ? sh[t - o] : 0;
        __syncthreads();
        sh[t] += y;
        __syncthreads();
    }
    if (t < NB) g_boff[t] = sh[t] - v;     // exclusive
    if (t == NB - 1) g_off[NN] = sh[NB - 1];
}

__global__ void k_scan2() {                // grid NB, block 1024
    __shared__ int wsum[32];
    int b = blockIdx.x, t = threadIdx.x, lane = t & 31, wid = t >> 5;
    int i = b * 1024 + t;
    int v = (i < NN) ? g_deg[i] : 0;
    int xsc = v;
#pragma unroll
    for (int o = 1; o < 32; o <<= 1) { int y = __shfl_up_sync(0xffffffffu, xsc, o); if (lane >= o) xsc += y; }
    if (lane == 31) wsum[wid] = xsc;
    __syncthreads();
    if (wid == 0) {
        int s = wsum[lane];
#pragma unroll
        for (int o = 1; o < 32; o <<= 1) { int y = __shfl_up_sync(0xffffffffu, s, o); if (lane >= o) s += y; }
        wsum[lane] = s;
    }
    __syncthreads();
    int prefix = g_boff[b] + (wid ? wsum[wid - 1] : 0) + xsc - v;   // exclusive
    if (i < NN) { g_off[i] = prefix; g_cur[i] = prefix; }
}

__global__ void k_scatter(const int* __restrict__ src, const int* __restrict__ dst) {
    int e = blockIdx.x * blockDim.x + threadIdx.x;
    if (e < EE) {
        int d = dst[e];
        int pos = atomicAdd(&g_cur[d], 1);
        g_esrc[pos] = src[e];
    }
}

// agg[n][f] = (hlr[n][f] + sum_in hlr[src][f]) / (1 + deg)  — 8 threads/node
__global__ void k_agg() {
    int idx = blockIdx.x * blockDim.x + threadIdx.x;
    if (idx >= NN * 8) return;
    int n = idx >> 3, f = idx & 7;
    int s = g_off[n], e = g_off[n + 1];
    float c = 0.f;
    for (int j = s; j < e; j++) c += g_hlr[g_esrc[j] * 8 + f];
    g_agg[idx] = (g_hlr[idx] + c) / (1.0f + (float)(e - s));
}

// ---------------- tf32 mma.sync GEMM: g_xvh = half(x @ Wv + bv) --------------
__device__ __forceinline__ uint32_t f2tf(float f) {
    uint32_t u;
    asm("cvt.rna.tf32.f32 %0, %1;" : "=r"(u) : "f"(f));
    return u;
}

__global__ void __launch_bounds__(256) k_gemm_mma(const float* __restrict__ A,
                                                  const float* __restrict__ bias) {
    __shared__ uint32_t As[4096];   // [kstep(4)][mtile(8)][reg(4)][lane(32)]
    __shared__ uint32_t Bs[4096];   // [kstep(4)][ntile(16)][reg(2)][lane(32)]
    int t = threadIdx.x, lane = t & 31, wid = t >> 5;
    int row0 = (int)(blockIdx.x >> 1) * 128;
    int col0 = (int)(blockIdx.x & 1) * 128;
    int warp_m = wid & 1, warp_n = wid >> 1;

    float acc[4][4][4];
#pragma unroll
    for (int mt = 0; mt < 4; mt++)
#pragma unroll
        for (int nt = 0; nt < 4; nt++)
#pragma unroll
            for (int j = 0; j < 4; j++) acc[mt][nt][j] = 0.f;

    int sAaddr[4], sBaddr[4], aRow[4], bRow[4], abCol[4];
#pragma unroll
    for (int l = 0; l < 4; l++) {
        int i = t + l * 256;
        int r = i >> 3, cq = i & 7;
        aRow[l] = r; bRow[l] = r; abCol[l] = cq * 4;
        int ks = cq >> 1, u = cq & 1;
        int mtile = r >> 4, h = (r >> 3) & 1, g = r & 7;
        sAaddr[l] = ((ks * 8 + mtile) * 4 + (h + 2 * u)) * 32 + g * 4;
        int ntile = r >> 3;
        sBaddr[l] = ((ks * 16 + ntile) * 2 + u) * 32 + (r & 7) * 4;
    }

    uint4 ap[4], bp[4];
#pragma unroll
    for (int l = 0; l < 4; l++) {
        int grow = row0 + aRow[l];
        float4 v = make_float4(0.f, 0.f, 0.f, 0.f);
        if (grow < NN) v = *(const float4*)(A + (size_t)grow * 256 + abCol[l]);
        ap[l] = make_uint4(f2tf(v.x), f2tf(v.y), f2tf(v.z), f2tf(v.w));
        float4 w = *(const float4*)(g_WvT + (size_t)(col0 + bRow[l]) * 256 + abCol[l]);
        bp[l] = make_uint4(f2tf(w.x), f2tf(w.y), f2tf(w.z), f2tf(w.w));
    }

    for (int c = 0; c < 8; c++) {
#pragma unroll
        for (int l = 0; l < 4; l++) {
            *(uint4*)&As[sAaddr[l]] = ap[l];
            *(uint4*)&Bs[sBaddr[l]] = bp[l];
        }
        __syncthreads();
        if (c < 7) {
            int k0 = (c + 1) * 32;
#pragma unroll
            for (int l = 0; l < 4; l++) {
                int grow = row0 + aRow[l];
                float4 v = make_float4(0.f, 0.f, 0.f, 0.f);
                if (grow < NN) v = *(const float4*)(A + (size_t)grow * 256 + k0 + abCol[l]);
                ap[l] = make_uint4(f2tf(v.x), f2tf(v.y), f2tf(v.z), f2tf(v.w));
                float4 w = *(const float4*)(g_WvT + (size_t)(col0 + bRow[l]) * 256 + k0 + abCol[l]);
                bp[l] = make_uint4(f2tf(w.x), f2tf(w.y), f2tf(w.z), f2tf(w.w));
            }
        }
#pragma unroll
        for (int ks = 0; ks < 4; ks++) {
            uint32_t a[4][4], b[4][2];
#pragma unroll
            for (int mt = 0; mt < 4; mt++)
#pragma unroll
                for (int rg = 0; rg < 4; rg++)
                    a[mt][rg] = As[((ks * 8 + warp_m * 4 + mt) * 4 + rg) * 32 + lane];
#pragma unroll
            for (int nt = 0; nt < 4; nt++)
#pragma unroll
                for (int rg = 0; rg < 2; rg++)
                    b[nt][rg] = Bs[((ks * 16 + warp_n * 4 + nt) * 2 + rg) * 32 + lane];
#pragma unroll
            for (int mt = 0; mt < 4; mt++)
#pragma unroll
                for (int nt = 0; nt < 4; nt++) {
                    asm volatile(
                        "mma.sync.aligned.m16n8k8.row.col.f32.tf32.tf32.f32 "
                        "{%0,%1,%2,%3}, {%4,%5,%6,%7}, {%8,%9}, {%0,%1,%2,%3};"
                        : "+f"(acc[mt][nt][0]), "+f"(acc[mt][nt][1]),
                          "+f"(acc[mt][nt][2]), "+f"(acc[mt][nt][3])
                        : "r"(a[mt][0]), "r"(a[mt][1]), "r"(a[mt][2]), "r"(a[mt][3]),
                          "r"(b[nt][0]), "r"(b[nt][1]));
                }
        }
        __syncthreads();
    }

    int g = lane >> 2, tig = lane & 3;
#pragma unroll
    for (int mt = 0; mt < 4; mt++) {
        int rbase = row0 + warp_m * 64 + mt * 16;
#pragma unroll
        for (int h = 0; h < 2; h++) {
            int grow = rbase + h * 8 + g;
            if (grow < NN) {
                __half* orow = g_xvh + (size_t)grow * 256;
#pragma unroll
                for (int nt = 0; nt < 4; nt++) {
                    int col = col0 + warp_n * 32 + nt * 8 + tig * 2;
                    float2 o;
                    o.x = acc[mt][nt][h * 2 + 0] + bias[col];
                    o.y = acc[mt][nt][h * 2 + 1] + bias[col + 1];
                    *(__half2*)(orow + col) = __floats2half2_rn(o.x, o.y);
                }
            }
        }
    }
}

// ---------------- attention + output (warp per dst node, no max pass) -------
__global__ void k_out(float* __restrict__ out) {
    int gw = (blockIdx.x * blockDim.x + threadIdx.x) >> 5;
    int lane = threadIdx.x & 31;
    if (gw >= NN) return;
    int s0 = g_off[gw], s1 = g_off[gw + 1];
    float4* orow = (float4*)(out + (size_t)gw * 256);
    if (s0 == s1) {
        float4 z = make_float4(0.f, 0.f, 0.f, 0.f);
        orow[lane] = z; orow[lane + 32] = z;
        return;
    }
    float srh[4];
#pragma unroll
    for (int h = 0; h < 4; h++) srh[h] = g_agg[gw * 8 + 4 + h];

    // single fused pass: exp(e) (no max shift; |e| bounded), denom, weighted xv
    float den0 = 0.f, den1 = 0.f, den2 = 0.f, den3 = 0.f;
    float4 acc0 = make_float4(0.f, 0.f, 0.f, 0.f);
    float4 acc1 = acc0;
    bool hi = (lane & 16) != 0;
    for (int j = s0; j < s1; j++) {
        int s = g_esrc[j];
        float e0 = g_agg[s * 8 + 0] + srh[0]; e0 = e0 > 0.f ? e0 : 0.2f * e0;
        float e1 = g_agg[s * 8 + 1] + srh[1]; e1 = e1 > 0.f ? e1 : 0.2f * e1;
        float e2 = g_agg[s * 8 + 2] + srh[2]; e2 = e2 > 0.f ? e2 : 0.2f * e2;
        float e3 = g_agg[s * 8 + 3] + srh[3]; e3 = e3 > 0.f ? e3 : 0.2f * e3;
        float x0 = __expf(e0);
        float x1 = __expf(e1);
        float x2 = __expf(e2);
        float x3 = __expf(e3);
        den0 += x0; den1 += x1; den2 += x2; den3 += x3;
        const uint2* vr = (const uint2*)(g_xvh + (size_t)s * 256);
        uint2 p0 = vr[lane], p1 = vr[lane + 32];
        float2 a0 = __half22float2(*(__half2*)&p0.x);
        float2 a1 = __half22float2(*(__half2*)&p0.y);
        float2 b0 = __half22float2(*(__half2*)&p1.x);
        float2 b1 = __half22float2(*(__half2*)&p1.y);
        float w0 = hi ? x1 : x0;
        float w1 = hi ? x3 : x2;
        acc0.x += w0 * a0.x; acc0.y += w0 * a0.y; acc0.z += w0 * a1.x; acc0.w += w0 * a1.y;
        acc1.x += w1 * b0.x; acc1.y += w1 * b0.y; acc1.z += w1 * b1.x; acc1.w += w1 * b1.y;
    }
    float d0 = hi ? den1 : den0;
    float d1 = hi ? den3 : den2;
    float i0 = 1.f / fmaxf(d0, 1e-16f);
    float i1 = 1.f / fmaxf(d1, 1e-16f);
    acc0.x *= i0; acc0.y *= i0; acc0.z *= i0; acc0.w *= i0;
    acc1.x *= i1; acc1.y *= i1; acc1.z *= i1; acc1.w *= i1;
    orow[lane] = acc0;
    orow[lane + 32] = acc1;
}

// ---------------- launch ----------------
extern "C" void kernel_launch(void* const* d_in, const int* in_sizes, int n_in,
                              void* d_out, int out_size) {
    const float* x    = (const float*)d_in[0];
    const int*   src  = (const int*)d_in[1];
    const int*   dst  = (const int*)d_in[2];
    const float* Wl   = (const float*)d_in[3];
    const float* bl   = (const float*)d_in[4];
    const float* Wr   = (const float*)d_in[5];
    const float* br   = (const float*)d_in[6];
    const float* Wv   = (const float*)d_in[7];
    const float* bv   = (const float*)d_in[8];
    const float* attl = (const float*)d_in[9];
    const float* attr = (const float*)d_in[10];
    float* out = (float*)d_out;

    k_setup<<<72 + (NN + 255) / 256, 256>>>(Wl, bl, Wr, br, attl, attr, Wv);
    k_hlr<<<(NN * 4 + 255) / 256, 256>>>(x);
    k_count<<<(EE + 255) / 256, 256>>>(dst);
    k_bsum<<<NB, 1024>>>();
    k_bscan<<<1, 64>>>();
    k_scan2<<<NB, 1024>>>();
    k_scatter<<<(EE + 255) / 256, 256>>>(src, dst);
    k_gemm_mma<<<((NN + 127) / 128) * 2, 256>>>(x, bv);
    k_agg<<<(NN * 8 + 255) / 256, 256>>>();
    k_out<<<(NN * 32 + 255) / 256, 256>>>(out);
}

// round 15
// speedup vs baseline: 1.1162x; 1.0208x over previous
#include <cuda_runtime.h>
#include <cuda_fp16.h>
#include <math.h>
#include <stdint.h>

#define NN 50000
#define EE 800000
#define CIN 256
#define COUT 256
#define NB 49            // scan blocks of 1024: 49*1024 = 50176 >= NN

// ---------------- scratch (static device globals; no allocation) -------------
__device__ __half g_xvh[(size_t)NN * 256]; // x @ Wv + bv  (fp16 storage)
__device__ float g_hlr[NN * 8];            // [sl(4) | sr(4)] raw
__device__ float g_agg[NN * 8];            // (hlr + conv)/(1+deg)
__device__ int   g_esrc[EE];               // src indices sorted by dst (CSR)
__device__ int   g_off[NN + 1];            // CSR offsets
__device__ int   g_cur[NN];                // scatter cursors
__device__ int   g_deg[NN];                // in-degree per dst
__device__ float g_watt[8 * 256];          // rows 0..3: Wl@att_l per head; 4..7: Wr@att_r
__device__ float g_batt[8];                // bias dotted with att vectors
__device__ float g_WvT[256 * 256];         // Wv transposed: g_WvT[n][k] = Wv[k][n]
__device__ int   g_bsum[64];               // per-block degree sums
__device__ int   g_boff[64];               // exclusive scan of block sums

// ---------------- fused setup: prep (blocks 0..7), trans (8..71), zero (72..)
__global__ void k_setup(const float* __restrict__ Wl, const float* __restrict__ bl,
                        const float* __restrict__ Wr, const float* __restrict__ br,
                        const float* __restrict__ attl, const float* __restrict__ attr,
                        const float* __restrict__ Wv) {
    int b = blockIdx.x;
    if (b < 8) {
        int o = b, h = o & 3;
        const float* W   = (o < 4) ? Wl : Wr;
        const float* att = (o < 4) ? attl : attr;
        const float* bb  = (o < 4) ? bl : br;
        int c = threadIdx.x;
        float s = 0.f;
#pragma unroll 8
        for (int d = 0; d < 64; d++) s += W[c * 256 + h * 64 + d] * att[h * 64 + d];
        g_watt[o * 256 + c] = s;
        if (c == 0) {
            float sb = 0.f;
            for (int d = 0; d < 64; d++) sb += bb[h * 64 + d] * att[h * 64 + d];
            g_batt[o] = sb;
        }
    } else if (b < 72) {
        __shared__ float tile[32][33];
        int bb2 = b - 8;
        int bx = bb2 & 7, by = bb2 >> 3;
        int tx = threadIdx.x & 31, ty = threadIdx.x >> 5;
#pragma unroll
        for (int i = 0; i < 32; i += 8)
            tile[ty + i][tx] = Wv[(by * 32 + ty + i) * 256 + bx * 32 + tx];
        __syncthreads();
#pragma unroll
        for (int i = 0; i < 32; i += 8)
            g_WvT[(bx * 32 + ty + i) * 256 + by * 32 + tx] = tile[tx][ty + i];
    } else {
        int i = (b - 72) * 256 + threadIdx.x;
        if (i < NN) g_deg[i] = 0;
    }
}

// per-node raw scores: 4 threads per node, 64 k each, shfl-reduce within quad.
// ws pitch-68 packing -> conflict-free LDS.128.
__global__ void __launch_bounds__(256) k_hlr(const float* __restrict__ x) {
    __shared__ __align__(16) float ws[32 * 68];
    int t = threadIdx.x;
    for (int i = t; i < 2048; i += 256) {
        int o = i >> 8, rem = i & 255, sub = rem >> 6, j = rem & 63;
        ws[(o * 4 + sub) * 68 + j] = g_watt[i];
    }
    __syncthreads();
    int g = blockIdx.x * 256 + t;
    int node = g >> 2, sub = g & 3;
    if (node >= NN) return;      // warp-aligned exit (200000 % 32 == 0)
    const float* xr = x + (size_t)node * 256 + sub * 64;
    const float* wr = ws + sub * 68;
    float acc[8] = {0.f, 0.f, 0.f, 0.f, 0.f, 0.f, 0.f, 0.f};
#pragma unroll
    for (int q = 0; q < 16; q += 4) {
        float4 xv[4];
#pragma unroll
        for (int u = 0; u < 4; u++) xv[u] = *(const float4*)(xr + (q + u) * 4);
#pragma unroll
        for (int o = 0; o < 8; o++) {
#pragma unroll
            for (int u = 0; u < 4; u++) {
                float4 w = *(const float4*)(wr + o * 272 + (q + u) * 4);
                acc[o] += xv[u].x * w.x + xv[u].y * w.y + xv[u].z * w.z + xv[u].w * w.w;
            }
        }
    }
#pragma unroll
    for (int o = 0; o < 8; o++) {
        acc[o] += __shfl_xor_sync(0xffffffffu, acc[o], 1);
        acc[o] += __shfl_xor_sync(0xffffffffu, acc[o], 2);
    }
    if (sub == 0) {
        float4 h0 = make_float4(acc[0] + g_batt[0], acc[1] + g_batt[1],
                                acc[2] + g_batt[2], acc[3] + g_batt[3]);
        float4 h1 = make_float4(acc[4] + g_batt[4], acc[5] + g_batt[5],
                                acc[6] + g_batt[6], acc[7] + g_batt[7]);
        *(float4*)&g_hlr[node * 8] = h0;
        *(float4*)&g_hlr[node * 8 + 4] = h1;
    }
}

__global__ void k_count(const int* __restrict__ dst) {
    int e = blockIdx.x * blockDim.x + threadIdx.x;
    if (e < EE) atomicAdd(&g_deg[dst[e]], 1);
}

// ---- parallel 3-phase exclusive scan of g_deg -> g_off, g_cur ----
__global__ void k_bsum() {                 // grid NB, block 1024
    __shared__ int ssum[32];
    int b = blockIdx.x, t = threadIdx.x;
    int i = b * 1024 + t;
    int v = (i < NN) ? g_deg[i] : 0;
#pragma unroll
    for (int o = 16; o; o >>= 1) v += __shfl_xor_sync(0xffffffffu, v, o);
    if ((t & 31) == 0) ssum[t >> 5] = v;
    __syncthreads();
    if (t < 32) {
        int s = ssum[t];
#pragma unroll
        for (int o = 16; o; o >>= 1) s += __shfl_xor_sync(0xffffffffu, s, o);
        if (t == 0) g_bsum[b] = s;
    }
}

__global__ void k_bscan() {                // 1 block, 64 threads
    __shared__ int sh[64];
    int t = threadIdx.x;
    int v = (t < NB) ? g_bsum[t] : 0;
    sh[t] = v;
    __syncthreads();
    for (int o = 1; o < 64; o <<= 1) {
        int y = (t >= o) ? sh[t - o] : 0;
        __syncthreads();
        sh[t] += y;
        __syncthreads();
    }
    if (t < NB) g_boff[t] = sh[t] - v;     // exclusive
    if (t == NB - 1) g_off[NN] = sh[NB - 1];
}

__global__ void k_scan2() {                // grid NB, block 1024
    __shared__ int wsum[32];
    int b = blockIdx.x, t = threadIdx.x, lane = t & 31, wid = t >> 5;
    int i = b * 1024 + t;
    int v = (i < NN) ? g_deg[i] : 0;
    int xsc = v;
#pragma unroll
    for (int o = 1; o < 32; o <<= 1) { int y = __shfl_up_sync(0xffffffffu, xsc, o); if (lane >= o) xsc += y; }
    if (lane == 31) wsum[wid] = xsc;
    __syncthreads();
    if (wid == 0) {
        int s = wsum[lane];
#pragma unroll
        for (int o = 1; o < 32; o <<= 1) { int y = __shfl_up_sync(0xffffffffu, s, o); if (lane >= o) s += y; }
        wsum[lane] = s;
    }
    __syncthreads();
    int prefix = g_boff[b] + (wid ? wsum[wid - 1] : 0) + xsc - v;   // exclusive
    if (i < NN) { g_off[i] = prefix; g_cur[i] = prefix; }
}

__global__ void k_scatter(const int* __restrict__ src, const int* __restrict__ dst) {
    int e = blockIdx.x * blockDim.x + threadIdx.x;
    if (e < EE) {
        int d = dst[e];
        int pos = atomicAdd(&g_cur[d], 1);
        g_esrc[pos] = src[e];
    }
}

// agg[n][f] = (hlr[n][f] + sum_in hlr[src][f]) / (1 + deg)  — 8 threads/node
__global__ void k_agg() {
    int idx = blockIdx.x * blockDim.x + threadIdx.x;
    if (idx >= NN * 8) return;
    int n = idx >> 3, f = idx & 7;
    int s = g_off[n], e = g_off[n + 1];
    float c = 0.f;
    for (int j = s; j < e; j++) c += g_hlr[g_esrc[j] * 8 + f];
    g_agg[idx] = (g_hlr[idx] + c) / (1.0f + (float)(e - s));
}

// ---------------- tf32 mma.sync GEMM: g_xvh = half(x @ Wv + bv) --------------
__device__ __forceinline__ uint32_t f2tf(float f) {
    uint32_t u;
    asm("cvt.rna.tf32.f32 %0, %1;" : "=r"(u) : "f"(f));
    return u;
}

__global__ void __launch_bounds__(256) k_gemm_mma(const float* __restrict__ A,
                                                  const float* __restrict__ bias) {
    __shared__ uint32_t As[4096];   // [kstep(4)][mtile(8)][reg(4)][lane(32)]
    __shared__ uint32_t Bs[4096];   // [kstep(4)][ntile(16)][reg(2)][lane(32)]
    int t = threadIdx.x, lane = t & 31, wid = t >> 5;
    int row0 = (int)(blockIdx.x >> 1) * 128;
    int col0 = (int)(blockIdx.x & 1) * 128;
    int warp_m = wid & 1, warp_n = wid >> 1;

    float acc[4][4][4];
#pragma unroll
    for (int mt = 0; mt < 4; mt++)
#pragma unroll
        for (int nt = 0; nt < 4; nt++)
#pragma unroll
            for (int j = 0; j < 4; j++) acc[mt][nt][j] = 0.f;

    int sAaddr[4], sBaddr[4], aRow[4], bRow[4], abCol[4];
#pragma unroll
    for (int l = 0; l < 4; l++) {
        int i = t + l * 256;
        int r = i >> 3, cq = i & 7;
        aRow[l] = r; bRow[l] = r; abCol[l] = cq * 4;
        int ks = cq >> 1, u = cq & 1;
        int mtile = r >> 4, h = (r >> 3) & 1, g = r & 7;
        sAaddr[l] = ((ks * 8 + mtile) * 4 + (h + 2 * u)) * 32 + g * 4;
        int ntile = r >> 3;
        sBaddr[l] = ((ks * 16 + ntile) * 2 + u) * 32 + (r & 7) * 4;
    }

    uint4 ap[4], bp[4];
#pragma unroll
    for (int l = 0; l < 4; l++) {
        int grow = row0 + aRow[l];
        float4 v = make_float4(0.f, 0.f, 0.f, 0.f);
        if (grow < NN) v = *(const float4*)(A + (size_t)grow * 256 + abCol[l]);
        ap[l] = make_uint4(f2tf(v.x), f2tf(v.y), f2tf(v.z), f2tf(v.w));
        float4 w = *(const float4*)(g_WvT + (size_t)(col0 + bRow[l]) * 256 + abCol[l]);
        bp[l] = make_uint4(f2tf(w.x), f2tf(w.y), f2tf(w.z), f2tf(w.w));
    }

    for (int c = 0; c < 8; c++) {
#pragma unroll
        for (int l = 0; l < 4; l++) {
            *(uint4*)&As[sAaddr[l]] = ap[l];
            *(uint4*)&Bs[sBaddr[l]] = bp[l];
        }
        __syncthreads();
        if (c < 7) {
            int k0 = (c + 1) * 32;
#pragma unroll
            for (int l = 0; l < 4; l++) {
                int grow = row0 + aRow[l];
                float4 v = make_float4(0.f, 0.f, 0.f, 0.f);
                if (grow < NN) v = *(const float4*)(A + (size_t)grow * 256 + k0 + abCol[l]);
                ap[l] = make_uint4(f2tf(v.x), f2tf(v.y), f2tf(v.z), f2tf(v.w));
                float4 w = *(const float4*)(g_WvT + (size_t)(col0 + bRow[l]) * 256 + k0 + abCol[l]);
                bp[l] = make_uint4(f2tf(w.x), f2tf(w.y), f2tf(w.z), f2tf(w.w));
            }
        }
#pragma unroll
        for (int ks = 0; ks < 4; ks++) {
            uint32_t a[4][4], b[4][2];
#pragma unroll
            for (int mt = 0; mt < 4; mt++)
#pragma unroll
                for (int rg = 0; rg < 4; rg++)
                    a[mt][rg] = As[((ks * 8 + warp_m * 4 + mt) * 4 + rg) * 32 + lane];
#pragma unroll
            for (int nt = 0; nt < 4; nt++)
#pragma unroll
                for (int rg = 0; rg < 2; rg++)
                    b[nt][rg] = Bs[((ks * 16 + warp_n * 4 + nt) * 2 + rg) * 32 + lane];
#pragma unroll
            for (int mt = 0; mt < 4; mt++)
#pragma unroll
                for (int nt = 0; nt < 4; nt++) {
                    asm volatile(
                        "mma.sync.aligned.m16n8k8.row.col.f32.tf32.tf32.f32 "
                        "{%0,%1,%2,%3}, {%4,%5,%6,%7}, {%8,%9}, {%0,%1,%2,%3};"
                        : "+f"(acc[mt][nt][0]), "+f"(acc[mt][nt][1]),
                          "+f"(acc[mt][nt][2]), "+f"(acc[mt][nt][3])
                        : "r"(a[mt][0]), "r"(a[mt][1]), "r"(a[mt][2]), "r"(a[mt][3]),
                          "r"(b[nt][0]), "r"(b[nt][1]));
                }
        }
        __syncthreads();
    }

    int g = lane >> 2, tig = lane & 3;
#pragma unroll
    for (int mt = 0; mt < 4; mt++) {
        int rbase = row0 + warp_m * 64 + mt * 16;
#pragma unroll
        for (int h = 0; h < 2; h++) {
            int grow = rbase + h * 8 + g;
            if (grow < NN) {
                __half* orow = g_xvh + (size_t)grow * 256;
#pragma unroll
                for (int nt = 0; nt < 4; nt++) {
                    int col = col0 + warp_n * 32 + nt * 8 + tig * 2;
                    float2 o;
                    o.x = acc[mt][nt][h * 2 + 0] + bias[col];
                    o.y = acc[mt][nt][h * 2 + 1] + bias[col + 1];
                    *(__half2*)(orow + col) = __floats2half2_rn(o.x, o.y);
                }
            }
        }
    }
}

// ---------------- attention + output (warp per dst node, no max pass) -------
__global__ void k_out(float* __restrict__ out) {
    int gw = (blockIdx.x * blockDim.x + threadIdx.x) >> 5;
    int lane = threadIdx.x & 31;
    if (gw >= NN) return;
    int s0 = g_off[gw], s1 = g_off[gw + 1];
    float4* orow = (float4*)(out + (size_t)gw * 256);
    if (s0 == s1) {
        float4 z = make_float4(0.f, 0.f, 0.f, 0.f);
        orow[lane] = z; orow[lane + 32] = z;
        return;
    }
    float4 sr4 = *(const float4*)&g_agg[gw * 8 + 4];

    float den0 = 0.f, den1 = 0.f, den2 = 0.f, den3 = 0.f;
    float4 acc0 = make_float4(0.f, 0.f, 0.f, 0.f);
    float4 acc1 = acc0;
    bool hi = (lane & 16) != 0;

    int j = s0;
    for (; j + 1 < s1; j += 2) {
        int sa = g_esrc[j], sb = g_esrc[j + 1];
        float4 aa = *(const float4*)&g_agg[sa * 8];
        float4 ab = *(const float4*)&g_agg[sb * 8];
        const uint2* vra = (const uint2*)(g_xvh + (size_t)sa * 256);
        const uint2* vrb = (const uint2*)(g_xvh + (size_t)sb * 256);
        uint2 pa0 = vra[lane], pa1 = vra[lane + 32];
        uint2 pb0 = vrb[lane], pb1 = vrb[lane + 32];

        float e0 = aa.x + sr4.x; e0 = fmaxf(e0, 0.2f * e0);
        float e1 = aa.y + sr4.y; e1 = fmaxf(e1, 0.2f * e1);
        float e2 = aa.z + sr4.z; e2 = fmaxf(e2, 0.2f * e2);
        float e3 = aa.w + sr4.w; e3 = fmaxf(e3, 0.2f * e3);
        float x0 = __expf(e0), x1 = __expf(e1), x2 = __expf(e2), x3 = __expf(e3);
        den0 += x0; den1 += x1; den2 += x2; den3 += x3;
        float w0 = hi ? x1 : x0;
        float w1 = hi ? x3 : x2;
        float2 a0 = __half22float2(*(__half2*)&pa0.x);
        float2 a1 = __half22float2(*(__half2*)&pa0.y);
        float2 b0 = __half22float2(*(__half2*)&pa1.x);
        float2 b1 = __half22float2(*(__half2*)&pa1.y);
        acc0.x += w0 * a0.x; acc0.y += w0 * a0.y; acc0.z += w0 * a1.x; acc0.w += w0 * a1.y;
        acc1.x += w1 * b0.x; acc1.y += w1 * b0.y; acc1.z += w1 * b1.x; acc1.w += w1 * b1.y;

        e0 = ab.x + sr4.x; e0 = fmaxf(e0, 0.2f * e0);
        e1 = ab.y + sr4.y; e1 = fmaxf(e1, 0.2f * e1);
        e2 = ab.z + sr4.z; e2 = fmaxf(e2, 0.2f * e2);
        e3 = ab.w + sr4.w; e3 = fmaxf(e3, 0.2f * e3);
        x0 = __expf(e0); x1 = __expf(e1); x2 = __expf(e2); x3 = __expf(e3);
        den0 += x0; den1 += x1; den2 += x2; den3 += x3;
        w0 = hi ? x1 : x0;
        w1 = hi ? x3 : x2;
        a0 = __half22float2(*(__half2*)&pb0.x);
        a1 = __half22float2(*(__half2*)&pb0.y);
        b0 = __half22float2(*(__half2*)&pb1.x);
        b1 = __half22float2(*(__half2*)&pb1.y);
        acc0.x += w0 * a0.x; acc0.y += w0 * a0.y; acc0.z += w0 * a1.x; acc0.w += w0 * a1.y;
        acc1.x += w1 * b0.x; acc1.y += w1 * b0.y; acc1.z += w1 * b1.x; acc1.w += w1 * b1.y;
    }
    if (j < s1) {
        int s = g_esrc[j];
        float4 aa = *(const float4*)&g_agg[s * 8];
        const uint2* vr = (const uint2*)(g_xvh + (size_t)s * 256);
        uint2 p0 = vr[lane], p1 = vr[lane + 32];
        float e0 = aa.x + sr4.x; e0 = fmaxf(e0, 0.2f * e0);
        float e1 = aa.y + sr4.y; e1 = fmaxf(e1, 0.2f * e1);
        float e2 = aa.z + sr4.z; e2 = fmaxf(e2, 0.2f * e2);
        float e3 = aa.w + sr4.w; e3 = fmaxf(e3, 0.2f * e3);
        float x0 = __expf(e0), x1 = __expf(e1), x2 = __expf(e2), x3 = __expf(e3);
        den0 += x0; den1 += x1; den2 += x2; den3 += x3;
        float w0 = hi ? x1 : x0;
        float w1 = hi ? x3 : x2;
        float2 a0 = __half22float2(*(__half2*)&p0.x);
        float2 a1 = __half22float2(*(__half2*)&p0.y);
        float2 b0 = __half22float2(*(__half2*)&p1.x);
        float2 b1 = __half22float2(*(__half2*)&p1.y);
        acc0.x += w0 * a0.x; acc0.y += w0 * a0.y; acc0.z += w0 * a1.x; acc0.w += w0 * a1.y;
        acc1.x += w1 * b0.x; acc1.y += w1 * b0.y; acc1.z += w1 * b1.x; acc1.w += w1 * b1.y;
    }
    float d0 = hi ? den1 : den0;
    float d1 = hi ? den3 : den2;
    float i0 = 1.f / fmaxf(d0, 1e-16f);
    float i1 = 1.f / fmaxf(d1, 1e-16f);
    acc0.x *= i0; acc0.y *= i0; acc0.z *= i0; acc0.w *= i0;
    acc1.x *= i1; acc1.y *= i1; acc1.z *= i1; acc1.w *= i1;
    orow[lane] = acc0;
    orow[lane + 32] = acc1;
}

// ---------------- launch ----------------
extern "C" void kernel_launch(void* const* d_in, const int* in_sizes, int n_in,
                              void* d_out, int out_size) {
    const float* x    = (const float*)d_in[0];
    const int*   src  = (const int*)d_in[1];
    const int*   dst  = (const int*)d_in[2];
    const float* Wl   = (const float*)d_in[3];
    const float* bl   = (const float*)d_in[4];
    const float* Wr   = (const float*)d_in[5];
    const float* br   = (const float*)d_in[6];
    const float* Wv   = (const float*)d_in[7];
    const float* bv   = (const float*)d_in[8];
    const float* attl = (const float*)d_in[9];
    const float* attr = (const float*)d_in[10];
    float* out = (float*)d_out;

    k_setup<<<72 + (NN + 255) / 256, 256>>>(Wl, bl, Wr, br, attl, attr, Wv);
    k_hlr<<<(NN * 4 + 255) / 256, 256>>>(x);
    k_count<<<(EE + 255) / 256, 256>>>(dst);
    k_gemm_mma<<<((NN + 127) / 128) * 2, 256>>>(x, bv);   // 4th launch -> profiled
    k_bsum<<<NB, 1024>>>();
    k_bscan<<<1, 64>>>();
    k_scan2<<<NB, 1024>>>();
    k_scatter<<<(EE + 255) / 256, 256>>>(src, dst);
    k_agg<<<(NN * 8 + 255) / 256, 256>>>();
    k_out<<<(NN * 32 + 255) / 256, 256>>>(out);
}

// round 16
// speedup vs baseline: 1.2139x; 1.0875x over previous
#include <cuda_runtime.h>
#include <cuda_fp16.h>
#include <math.h>
#include <stdint.h>

#define NN 50000
#define NPAD 50176       // 392 * 128
#define EE 800000
#define CIN 256
#define COUT 256
#define NB 49            // scan blocks of 1024: 49*1024 = 50176 >= NN

// ---------------- scratch (static device globals; no allocation) -------------
__device__ __half g_xvh[(size_t)NN * 256]; // x @ Wv + bv  (fp16 storage)
__device__ uint32_t g_xtf[(size_t)NPAD * 256]; // x as tf32 bits (padded rows zero)
__device__ float g_hlr[NN * 8];            // [sl(4) | sr(4)] raw
__device__ float g_agg[NN * 8];            // (hlr + conv)/(1+deg)
__device__ int   g_esrc[EE];               // src indices sorted by dst (CSR)
__device__ int   g_off[NN + 1];            // CSR offsets
__device__ int   g_cur[NN];                // scatter cursors
__device__ int   g_deg[NN];                // in-degree per dst
__device__ float g_watt[8 * 256];          // rows 0..3: Wl@att_l per head; 4..7: Wr@att_r
__device__ float g_batt[8];                // bias dotted with att vectors
__device__ uint32_t g_WvT[256 * 256];      // Wv transposed, tf32 bits
__device__ int   g_bsum[64];               // per-block degree sums
__device__ int   g_boff[64];               // exclusive scan of block sums

__device__ __forceinline__ uint32_t f2tf(float f) {
    uint32_t u;
    asm("cvt.rna.tf32.f32 %0, %1;" : "=r"(u) : "f"(f));
    return u;
}
__device__ __forceinline__ uint32_t smem_u32(const void* p) {
    uint32_t a;
    asm("{ .reg .u64 t; cvta.to.shared.u64 t, %1; cvt.u32.u64 %0, t; }" : "=r"(a) : "l"(p));
    return a;
}
__device__ __forceinline__ void cpa16(uint32_t s, const void* g) {
    asm volatile("cp.async.ca.shared.global [%0], [%1], 16;" :: "r"(s), "l"(g));
}

// ---------------- fused setup: prep (blocks 0..7), trans (8..71), zero (72..)
__global__ void k_setup(const float* __restrict__ Wl, const float* __restrict__ bl,
                        const float* __restrict__ Wr, const float* __restrict__ br,
                        const float* __restrict__ attl, const float* __restrict__ attr,
                        const float* __restrict__ Wv) {
    int b = blockIdx.x;
    if (b < 8) {
        int o = b, h = o & 3;
        const float* W   = (o < 4) ? Wl : Wr;
        const float* att = (o < 4) ? attl : attr;
        const float* bb  = (o < 4) ? bl : br;
        int c = threadIdx.x;
        float s = 0.f;
#pragma unroll 8
        for (int d = 0; d < 64; d++) s += W[c * 256 + h * 64 + d] * att[h * 64 + d];
        g_watt[o * 256 + c] = s;
        if (c == 0) {
            float sb = 0.f;
            for (int d = 0; d < 64; d++) sb += bb[h * 64 + d] * att[h * 64 + d];
            g_batt[o] = sb;
        }
    } else if (b < 72) {
        __shared__ float tile[32][33];
        int bb2 = b - 8;
        int bx = bb2 & 7, by = bb2 >> 3;
        int tx = threadIdx.x & 31, ty = threadIdx.x >> 5;
#pragma unroll
        for (int i = 0; i < 32; i += 8)
            tile[ty + i][tx] = Wv[(by * 32 + ty + i) * 256 + bx * 32 + tx];
        __syncthreads();
#pragma unroll
        for (int i = 0; i < 32; i += 8)
            g_WvT[(bx * 32 + ty + i) * 256 + by * 32 + tx] = f2tf(tile[tx][ty + i]);
    } else {
        int i = (b - 72) * 256 + threadIdx.x;
        if (i < NN) g_deg[i] = 0;
    }
}

// per-node raw scores: 4 threads per node, 64 k each, shfl-reduce within quad.
// ws pitch-68 packing -> conflict-free LDS.128. Also emits g_xtf (tf32 bits).
__global__ void __launch_bounds__(256) k_hlr(const float* __restrict__ x) {
    __shared__ __align__(16) float ws[32 * 68];
    int t = threadIdx.x;
    for (int i = t; i < 2048; i += 256) {
        int o = i >> 8, rem = i & 255, sub = rem >> 6, j = rem & 63;
        ws[(o * 4 + sub) * 68 + j] = g_watt[i];
    }
    __syncthreads();
    int g = blockIdx.x * 256 + t;
    int node = g >> 2, sub = g & 3;
    if (node >= NN) return;      // warp-aligned exit (200000 % 32 == 0)
    const float* xr = x + (size_t)node * 256 + sub * 64;
    uint32_t* xo = g_xtf + (size_t)node * 256 + sub * 64;
    const float* wr = ws + sub * 68;
    float acc[8] = {0.f, 0.f, 0.f, 0.f, 0.f, 0.f, 0.f, 0.f};
#pragma unroll
    for (int q = 0; q < 16; q += 4) {
        float4 xv[4];
#pragma unroll
        for (int u = 0; u < 4; u++) {
            xv[u] = *(const float4*)(xr + (q + u) * 4);
            uint4 cv = make_uint4(f2tf(xv[u].x), f2tf(xv[u].y), f2tf(xv[u].z), f2tf(xv[u].w));
            *(uint4*)(xo + (q + u) * 4) = cv;
        }
#pragma unroll
        for (int o = 0; o < 8; o++) {
#pragma unroll
            for (int u = 0; u < 4; u++) {
                float4 w = *(const float4*)(wr + o * 272 + (q + u) * 4);
                acc[o] += xv[u].x * w.x + xv[u].y * w.y + xv[u].z * w.z + xv[u].w * w.w;
            }
        }
    }
#pragma unroll
    for (int o = 0; o < 8; o++) {
        acc[o] += __shfl_xor_sync(0xffffffffu, acc[o], 1);
        acc[o] += __shfl_xor_sync(0xffffffffu, acc[o], 2);
    }
    if (sub == 0) {
        float4 h0 = make_float4(acc[0] + g_batt[0], acc[1] + g_batt[1],
                                acc[2] + g_batt[2], acc[3] + g_batt[3]);
        float4 h1 = make_float4(acc[4] + g_batt[4], acc[5] + g_batt[5],
                                acc[6] + g_batt[6], acc[7] + g_batt[7]);
        *(float4*)&g_hlr[node * 8] = h0;
        *(float4*)&g_hlr[node * 8 + 4] = h1;
    }
}

__global__ void k_count(const int* __restrict__ dst) {
    int e = blockIdx.x * blockDim.x + threadIdx.x;
    if (e < EE) atomicAdd(&g_deg[dst[e]], 1);
}

// ---- parallel 3-phase exclusive scan of g_deg -> g_off, g_cur ----
__global__ void k_bsum() {
    __shared__ int ssum[32];
    int b = blockIdx.x, t = threadIdx.x;
    int i = b * 1024 + t;
    int v = (i < NN) ? g_deg[i] : 0;
#pragma unroll
    for (int o = 16; o; o >>= 1) v += __shfl_xor_sync(0xffffffffu, v, o);
    if ((t & 31) == 0) ssum[t >> 5] = v;
    __syncthreads();
    if (t < 32) {
        int s = ssum[t];
#pragma unroll
        for (int o = 16; o; o >>= 1) s += __shfl_xor_sync(0xffffffffu, s, o);
        if (t == 0) g_bsum[b] = s;
    }
}

__global__ void k_bscan() {
    __shared__ int sh[64];
    int t = threadIdx.x;
    int v = (t < NB) ? g_bsum[t] : 0;
    sh[t] = v;
    __syncthreads();
    for (int o = 1; o < 64; o <<= 1) {
        int y = (t >= o) ? sh[t - o] : 0;
        __syncthreads();
        sh[t] += y;
        __syncthreads();
    }
    if (t < NB) g_boff[t] = sh[t] - v;
    if (t == NB - 1) g_off[NN] = sh[NB - 1];
}

__global__ void k_scan2() {
    __shared__ int wsum[32];
    int b = blockIdx.x, t = threadIdx.x, lane = t & 31, wid = t >> 5;
    int i = b * 1024 + t;
    int v = (i < NN) ? g_deg[i] : 0;
    int xsc = v;
#pragma unroll
    for (int o = 1; o < 32; o <<= 1) { int y = __shfl_up_sync(0xffffffffu, xsc, o); if (lane >= o) xsc += y; }
    if (lane == 31) wsum[wid] = xsc;
    __syncthreads();
    if (wid == 0) {
        int s = wsum[lane];
#pragma unroll
        for (int o = 1; o < 32; o <<= 1) { int y = __shfl_up_sync(0xffffffffu, s, o); if (lane >= o) s += y; }
        wsum[lane] = s;
    }
    __syncthreads();
    int prefix = g_boff[b] + (wid ? wsum[wid - 1] : 0) + xsc - v;
    if (i < NN) { g_off[i] = prefix; g_cur[i] = prefix; }
}

__global__ void k_scatter(const int* __restrict__ src, const int* __restrict__ dst) {
    int e = blockIdx.x * blockDim.x + threadIdx.x;
    if (e < EE) {
        int d = dst[e];
        int pos = atomicAdd(&g_cur[d], 1);
        g_esrc[pos] = src[e];
    }
}

// agg[n][f] = (hlr[n][f] + sum_in hlr[src][f]) / (1 + deg)  — 8 threads/node
__global__ void k_agg() {
    int idx = blockIdx.x * blockDim.x + threadIdx.x;
    if (idx >= NN * 8) return;
    int n = idx >> 3, f = idx & 7;
    int s = g_off[n], e = g_off[n + 1];
    float c = 0.f;
    for (int j = s; j < e; j++) c += g_hlr[g_esrc[j] * 8 + f];
    g_agg[idx] = (g_hlr[idx] + c) / (1.0f + (float)(e - s));
}

// ---------------- tf32 mma.sync GEMM v2: cp.async double-buffered, BK=16 -----
// A = g_xtf (tf32 bits, NPAD x 256), B = g_WvT (tf32 bits). 2 CTAs/SM.
__global__ void __launch_bounds__(256, 2) k_gemm_mma(const float* __restrict__ bias) {
    __shared__ uint32_t As[2][2048];   // per chunk: 128 rows x 16 k, fragment layout
    __shared__ uint32_t Bs[2][2048];   // per chunk: 128 cols x 16 k
    int t = threadIdx.x, lane = t & 31, wid = t >> 5;
    int row0 = (int)(blockIdx.x >> 1) * 128;
    int col0 = (int)(blockIdx.x & 1) * 128;
    int warp_m = wid & 1, warp_n = wid >> 1;

    float acc[4][4][4];
#pragma unroll
    for (int mt = 0; mt < 4; mt++)
#pragma unroll
        for (int nt = 0; nt < 4; nt++)
#pragma unroll
            for (int j = 0; j < 4; j++) acc[mt][nt][j] = 0.f;

    // per-thread copy slots: i in {t, t+256}; r = i>>2 (0..127), cq = i&3
    uint32_t sA[2], sB[2];
    const uint32_t* gA[2];
    const uint32_t* gB[2];
#pragma unroll
    for (int l = 0; l < 2; l++) {
        int i = t + l * 256;
        int r = i >> 2, cq = i & 3;
        int ks = cq >> 1, u = cq & 1;
        int aoff = ((ks * 8 + (r >> 4)) * 4 + (((r >> 3) & 1) + 2 * u)) * 32 + (r & 7) * 4;
        int boff = ((ks * 16 + (r >> 3)) * 2 + u) * 32 + (r & 7) * 4;
        sA[l] = smem_u32(&As[0][aoff]);
        sB[l] = smem_u32(&Bs[0][boff]);
        gA[l] = g_xtf + (size_t)(row0 + r) * 256 + cq * 4;
        gB[l] = g_WvT + (size_t)(col0 + r) * 256 + cq * 4;
    }

    // prologue: chunk 0
#pragma unroll
    for (int l = 0; l < 2; l++) {
        cpa16(sA[l], gA[l]);
        cpa16(sB[l], gB[l]);
    }
    asm volatile("cp.async.commit_group;" ::: "memory");

    for (int c = 0; c < 16; c++) {
        int buf = c & 1;
        if (c < 15) {
            int nbuf = (c + 1) & 1;
            int k0 = (c + 1) * 16;
#pragma unroll
            for (int l = 0; l < 2; l++) {
                cpa16(sA[l] + nbuf * 8192, gA[l] + k0);
                cpa16(sB[l] + nbuf * 8192, gB[l] + k0);
            }
            asm volatile("cp.async.commit_group;" ::: "memory");
            asm volatile("cp.async.wait_group 1;" ::: "memory");
        } else {
            asm volatile("cp.async.wait_group 0;" ::: "memory");
        }
        __syncthreads();
#pragma unroll
        for (int ks = 0; ks < 2; ks++) {
            uint32_t a[4][4], b[4][2];
#pragma unroll
            for (int mt = 0; mt < 4; mt++)
#pragma unroll
                for (int rg = 0; rg < 4; rg++)
                    a[mt][rg] = As[buf][((ks * 8 + warp_m * 4 + mt) * 4 + rg) * 32 + lane];
#pragma unroll
            for (int nt = 0; nt < 4; nt++)
#pragma unroll
                for (int rg = 0; rg < 2; rg++)
                    b[nt][rg] = Bs[buf][((ks * 16 + warp_n * 4 + nt) * 2 + rg) * 32 + lane];
#pragma unroll
            for (int mt = 0; mt < 4; mt++)
#pragma unroll
                for (int nt = 0; nt < 4; nt++) {
                    asm volatile(
                        "mma.sync.aligned.m16n8k8.row.col.f32.tf32.tf32.f32 "
                        "{%0,%1,%2,%3}, {%4,%5,%6,%7}, {%8,%9}, {%0,%1,%2,%3};"
                        : "+f"(acc[mt][nt][0]), "+f"(acc[mt][nt][1]),
                          "+f"(acc[mt][nt][2]), "+f"(acc[mt][nt][3])
                        : "r"(a[mt][0]), "r"(a[mt][1]), "r"(a[mt][2]), "r"(a[mt][3]),
                          "r"(b[nt][0]), "r"(b[nt][1]));
                }
        }
        __syncthreads();
    }

    int g = lane >> 2, tig = lane & 3;
#pragma unroll
    for (int mt = 0; mt < 4; mt++) {
        int rbase = row0 + warp_m * 64 + mt * 16;
#pragma unroll
        for (int h = 0; h < 2; h++) {
            int grow = rbase + h * 8 + g;
            if (grow < NN) {
                __half* orow = g_xvh + (size_t)grow * 256;
#pragma unroll
                for (int nt = 0; nt < 4; nt++) {
                    int col = col0 + warp_n * 32 + nt * 8 + tig * 2;
                    float2 o;
                    o.x = acc[mt][nt][h * 2 + 0] + bias[col];
                    o.y = acc[mt][nt][h * 2 + 1] + bias[col + 1];
                    *(__half2*)(orow + col) = __floats2half2_rn(o.x, o.y);
                }
            }
        }
    }
}

// ---------------- attention + output (warp per dst node, no max pass) -------
__global__ void k_out(float* __restrict__ out) {
    int gw = (blockIdx.x * blockDim.x + threadIdx.x) >> 5;
    int lane = threadIdx.x & 31;
    if (gw >= NN) return;
    int s0 = g_off[gw], s1 = g_off[gw + 1];
    float4* orow = (float4*)(out + (size_t)gw * 256);
    if (s0 == s1) {
        float4 z = make_float4(0.f, 0.f, 0.f, 0.f);
        orow[lane] = z; orow[lane + 32] = z;
        return;
    }
    float4 sr4 = *(const float4*)&g_agg[gw * 8 + 4];

    float den0 = 0.f, den1 = 0.f, den2 = 0.f, den3 = 0.f;
    float4 acc0 = make_float4(0.f, 0.f, 0.f, 0.f);
    float4 acc1 = acc0;
    bool hi = (lane & 16) != 0;

    int j = s0;
    for (; j + 1 < s1; j += 2) {
        int sa = g_esrc[j], sb = g_esrc[j + 1];
        float4 aa = *(const float4*)&g_agg[sa * 8];
        float4 ab = *(const float4*)&g_agg[sb * 8];
        const uint2* vra = (const uint2*)(g_xvh + (size_t)sa * 256);
        const uint2* vrb = (const uint2*)(g_xvh + (size_t)sb * 256);
        uint2 pa0 = vra[lane], pa1 = vra[lane + 32];
        uint2 pb0 = vrb[lane], pb1 = vrb[lane + 32];

        float e0 = aa.x + sr4.x; e0 = fmaxf(e0, 0.2f * e0);
        float e1 = aa.y + sr4.y; e1 = fmaxf(e1, 0.2f * e1);
        float e2 = aa.z + sr4.z; e2 = fmaxf(e2, 0.2f * e2);
        float e3 = aa.w + sr4.w; e3 = fmaxf(e3, 0.2f * e3);
        float x0 = __expf(e0), x1 = __expf(e1), x2 = __expf(e2), x3 = __expf(e3);
        den0 += x0; den1 += x1; den2 += x2; den3 += x3;
        float w0 = hi ? x1 : x0;
        float w1 = hi ? x3 : x2;
        float2 a0 = __half22float2(*(__half2*)&pa0.x);
        float2 a1 = __half22float2(*(__half2*)&pa0.y);
        float2 b0 = __half22float2(*(__half2*)&pa1.x);
        float2 b1 = __half22float2(*(__half2*)&pa1.y);
        acc0.x += w0 * a0.x; acc0.y += w0 * a0.y; acc0.z += w0 * a1.x; acc0.w += w0 * a1.y;
        acc1.x += w1 * b0.x; acc1.y += w1 * b0.y; acc1.z += w1 * b1.x; acc1.w += w1 * b1.y;

        e0 = ab.x + sr4.x; e0 = fmaxf(e0, 0.2f * e0);
        e1 = ab.y + sr4.y; e1 = fmaxf(e1, 0.2f * e1);
        e2 = ab.z + sr4.z; e2 = fmaxf(e2, 0.2f * e2);
        e3 = ab.w + sr4.w; e3 = fmaxf(e3, 0.2f * e3);
        x0 = __expf(e0); x1 = __expf(e1); x2 = __expf(e2); x3 = __expf(e3);
        den0 += x0; den1 += x1; den2 += x2; den3 += x3;
        w0 = hi ? x1 : x0;
        w1 = hi ? x3 : x2;
        a0 = __half22float2(*(__half2*)&pb0.x);
        a1 = __half22float2(*(__half2*)&pb0.y);
        b0 = __half22float2(*(__half2*)&pb1.x);
        b1 = __half22float2(*(__half2*)&pb1.y);
        acc0.x += w0 * a0.x; acc0.y += w0 * a0.y; acc0.z += w0 * a1.x; acc0.w += w0 * a1.y;
        acc1.x += w1 * b0.x; acc1.y += w1 * b0.y; acc1.z += w1 * b1.x; acc1.w += w1 * b1.y;
    }
    if (j < s1) {
        int s = g_esrc[j];
        float4 aa = *(const float4*)&g_agg[s * 8];
        const uint2* vr = (const uint2*)(g_xvh + (size_t)s * 256);
        uint2 p0 = vr[lane], p1 = vr[lane + 32];
        float e0 = aa.x + sr4.x; e0 = fmaxf(e0, 0.2f * e0);
        float e1 = aa.y + sr4.y; e1 = fmaxf(e1, 0.2f * e1);
        float e2 = aa.z + sr4.z; e2 = fmaxf(e2, 0.2f * e2);
        float e3 = aa.w + sr4.w; e3 = fmaxf(e3, 0.2f * e3);
        float x0 = __expf(e0), x1 = __expf(e1), x2 = __expf(e2), x3 = __expf(e3);
        den0 += x0; den1 += x1; den2 += x2; den3 += x3;
        float w0 = hi ? x1 : x0;
        float w1 = hi ? x3 : x2;
        float2 a0 = __half22float2(*(__half2*)&p0.x);
        float2 a1 = __half22float2(*(__half2*)&p0.y);
        float2 b0 = __half22float2(*(__half2*)&p1.x);
        float2 b1 = __half22float2(*(__half2*)&p1.y);
        acc0.x += w0 * a0.x; acc0.y += w0 * a0.y; acc0.z += w0 * a1.x; acc0.w += w0 * a1.y;
        acc1.x += w1 * b0.x; acc1.y += w1 * b0.y; acc1.z += w1 * b1.x; acc1.w += w1 * b1.y;
    }
    float d0 = hi ? den1 : den0;
    float d1 = hi ? den3 : den2;
    float i0 = 1.f / fmaxf(d0, 1e-16f);
    float i1 = 1.f / fmaxf(d1, 1e-16f);
    acc0.x *= i0; acc0.y *= i0; acc0.z *= i0; acc0.w *= i0;
    acc1.x *= i1; acc1.y *= i1; acc1.z *= i1; acc1.w *= i1;
    orow[lane] = acc0;
    orow[lane + 32] = acc1;
}

// ---------------- launch ----------------
extern "C" void kernel_launch(void* const* d_in, const int* in_sizes, int n_in,
                              void* d_out, int out_size) {
    const float* x    = (const float*)d_in[0];
    const int*   src  = (const int*)d_in[1];
    const int*   dst  = (const int*)d_in[2];
    const float* Wl   = (const float*)d_in[3];
    const float* bl   = (const float*)d_in[4];
    const float* Wr   = (const float*)d_in[5];
    const float* br   = (const float*)d_in[6];
    const float* Wv   = (const float*)d_in[7];
    const float* bv   = (const float*)d_in[8];
    const float* attl = (const float*)d_in[9];
    const float* attr = (const float*)d_in[10];
    float* out = (float*)d_out;

    k_setup<<<72 + (NN + 255) / 256, 256>>>(Wl, bl, Wr, br, attl, attr, Wv);
    k_hlr<<<(NN * 4 + 255) / 256, 256>>>(x);
    k_count<<<(EE + 255) / 256, 256>>>(dst);
    k_gemm_mma<<<(NPAD / 128) * 2, 256>>>(bv);   // 4th launch -> profiled
    k_bsum<<<NB, 1024>>>();
    k_bscan<<<1, 64>>>();
    k_scan2<<<NB, 1024>>>();
    k_scatter<<<(EE + 255) / 256, 256>>>(src, dst);
    k_agg<<<(NN * 8 + 255) / 256, 256>>>();
    k_out<<<(NN * 32 + 255) / 256, 256>>>(out);
}